// round 3
// baseline (speedup 1.0000x reference)
#include <cuda_runtime.h>
#include <cstdint>

// Problem constants
static constexpr int B_  = 8;
static constexpr int T_  = 2048;
static constexpr int C_  = 1024;
static constexpr int H_  = 16;
static constexpr int D_  = 64;
static constexpr int TC3 = 3 * C_;   // 3072
static constexpr int M_  = B_ * T_;  // 16384

// Scratch q,k,v in (B,H,T,D) layout (device globals: allowed)
__device__ float g_q[(size_t)B_ * H_ * T_ * D_];
__device__ float g_k[(size_t)B_ * H_ * T_ * D_];
__device__ float g_v[(size_t)B_ * H_ * T_ * D_];

// ---------------------------------------------------------------------------
// PTX helpers
// ---------------------------------------------------------------------------
__device__ __forceinline__ uint32_t f2tf(float f) {
    uint32_t u;
    asm("cvt.rna.tf32.f32 %0, %1;" : "=r"(u) : "f"(f));
    return u;
}
__device__ __forceinline__ uint32_t sptr(const void* p) {
    return (uint32_t)__cvta_generic_to_shared(p);
}
__device__ __forceinline__ void ldsm4(uint32_t& r0, uint32_t& r1,
                                      uint32_t& r2, uint32_t& r3, uint32_t a) {
    asm volatile("ldmatrix.sync.aligned.m8n8.x4.shared.b16 {%0,%1,%2,%3}, [%4];"
                 : "=r"(r0), "=r"(r1), "=r"(r2), "=r"(r3) : "r"(a));
}
__device__ __forceinline__ void mma_tf32(float* d, const uint32_t* a,
                                         const uint32_t* b) {
    asm volatile(
        "mma.sync.aligned.m16n8k8.row.col.f32.tf32.tf32.f32 "
        "{%0,%1,%2,%3}, {%4,%5,%6,%7}, {%8,%9}, {%0,%1,%2,%3};"
        : "+f"(d[0]), "+f"(d[1]), "+f"(d[2]), "+f"(d[3])
        : "r"(a[0]), "r"(a[1]), "r"(a[2]), "r"(a[3]), "r"(b[0]), "r"(b[1]));
}

// ---------------------------------------------------------------------------
// Kernel 1: qkv = x @ W + b, tf32 mma, scatter to g_q/g_k/g_v (B,H,T,D)
// 128x128x16 tile, 8 warps (2M x 4N), warp tile 64x32.
// ---------------------------------------------------------------------------
__global__ __launch_bounds__(256) void qkv_gemm_kernel(
    const float* __restrict__ x,      // (M_, C_)
    const float* __restrict__ W,      // (C_, TC3)
    const float* __restrict__ bias)   // (TC3,)
{
    __shared__ float As[128 * 20];    // [m][k] stride 20 (conflict-free LDSM)
    __shared__ float Bt[128 * 20];    // [n][k] stride 20 (transposed W tile)

    const int bm = blockIdx.y, bn = blockIdx.x;
    const int tid = threadIdx.x;
    const int wid = tid >> 5, lane = tid & 31;
    const int wm = wid >> 2, wn = wid & 3;          // 2 x 4 warp grid
    const int q = lane & 3, r = lane >> 2;

    float acc[4][4][4];
#pragma unroll
    for (int i = 0; i < 4; ++i)
#pragma unroll
        for (int j = 0; j < 4; ++j)
#pragma unroll
            for (int k = 0; k < 4; ++k) acc[i][j][k] = 0.f;

    // LDSM source addresses (fixed per thread, advance by kstep offset)
    const int a_row = wm * 64 + (lane & 15);
    const int a_col = (lane >> 4) << 2;
    const int b_row_base = wn * 32 + (lane & 7) + ((lane & 16) ? 8 : 0);
    const int b_col = (lane & 8) ? 4 : 0;

    for (int k0 = 0; k0 < C_; k0 += 16) {
        // Stage A tile (128 x 16), cvt to tf32
#pragma unroll
        for (int i = 0; i < 2; ++i) {
            int f = tid + i * 256;
            int row = f >> 2, kc = (f & 3) << 2;
            float4 v = *(const float4*)(x + (size_t)(bm * 128 + row) * C_ + k0 + kc);
            uint4 u = {f2tf(v.x), f2tf(v.y), f2tf(v.z), f2tf(v.w)};
            *(uint4*)&As[row * 20 + kc] = u;
        }
        // Stage B tile (16 x 128) transposed to [n][k], cvt to tf32
#pragma unroll
        for (int i = 0; i < 2; ++i) {
            int f = tid + i * 256;
            int kr = f >> 5, c4 = (f & 31) << 2;
            float4 v = *(const float4*)(W + (size_t)(k0 + kr) * TC3 + bn * 128 + c4);
            Bt[(c4 + 0) * 20 + kr] = __uint_as_float(f2tf(v.x));
            Bt[(c4 + 1) * 20 + kr] = __uint_as_float(f2tf(v.y));
            Bt[(c4 + 2) * 20 + kr] = __uint_as_float(f2tf(v.z));
            Bt[(c4 + 3) * 20 + kr] = __uint_as_float(f2tf(v.w));
        }
        __syncthreads();

#pragma unroll
        for (int ks = 0; ks < 2; ++ks) {
            uint32_t af[4][4];
#pragma unroll
            for (int mt = 0; mt < 4; ++mt)
                ldsm4(af[mt][0], af[mt][1], af[mt][2], af[mt][3],
                      sptr(&As[(a_row + mt * 16) * 20 + ks * 8 + a_col]));
            uint32_t bf[4][2];
#pragma unroll
            for (int np = 0; np < 2; ++np) {
                uint32_t r0, r1, r2, r3;
                ldsm4(r0, r1, r2, r3,
                      sptr(&Bt[(b_row_base + np * 16) * 20 + ks * 8 + b_col]));
                bf[np * 2][0] = r0;     bf[np * 2][1] = r1;
                bf[np * 2 + 1][0] = r2; bf[np * 2 + 1][1] = r3;
            }
#pragma unroll
            for (int mt = 0; mt < 4; ++mt)
#pragma unroll
                for (int nt = 0; nt < 4; ++nt)
                    mma_tf32(acc[mt][nt], af[mt], bf[nt]);
        }
        __syncthreads();
    }

    // Epilogue: bias + scatter. `which` is uniform per CTA (BN=128 divides 1024)
    const int which = (bn * 128) >> 10;
    float* dst = (which == 0) ? g_q : (which == 1) ? g_k : g_v;
#pragma unroll
    for (int mt = 0; mt < 4; ++mt) {
#pragma unroll
        for (int half = 0; half < 2; ++half) {
            int m = bm * 128 + wm * 64 + mt * 16 + r + half * 8;
            int bb = m >> 11, tt = m & 2047;
#pragma unroll
            for (int nt = 0; nt < 4; ++nt) {
                int n = bn * 128 + wn * 32 + nt * 8 + 2 * q;
                int cc = n & 1023;
                int hh = cc >> 6, dd = cc & 63;
                float2 bv = *(const float2*)(bias + n);
                float2 o;
                o.x = acc[mt][nt][half * 2 + 0] + bv.x;
                o.y = acc[mt][nt][half * 2 + 1] + bv.y;
                *(float2*)(dst + ((size_t)(bb * H_ + hh) * T_ + tt) * D_ + dd) = o;
            }
        }
    }
}

// ---------------------------------------------------------------------------
// Kernel 2: flash attention with tf32 mma. CTA = (b, h, 128 q-rows), 8 warps,
// each warp owns 16 q-rows. Online softmax over 64-key blocks.
// ---------------------------------------------------------------------------
static constexpr int QS_STRIDE = 68;
static constexpr int AT_SMEM_BYTES =
    (128 * QS_STRIDE + 64 * QS_STRIDE + 64 * QS_STRIDE) * 4 + 64 * 4;

__global__ __launch_bounds__(256) void attn_kernel(
    const int* __restrict__ mask,     // (B_, T_)
    float* __restrict__ out)
{
    extern __shared__ float sm[];
    float* Qs = sm;                       // [128][68]  (aliased as Ps after Q-frag load)
    float* Ps = sm;
    float* Ks = sm + 128 * QS_STRIDE;     // [krow][d]  [64][68]
    float* Vt = Ks + 64 * QS_STRIDE;      // [d][krow]  [64][68] (transposed)
    int*   mk = (int*)(Vt + 64 * QS_STRIDE);

    const int qb = blockIdx.x, h = blockIdx.y, b = blockIdx.z;
    const int tid = threadIdx.x;
    const int wid = tid >> 5, lane = tid & 31;
    const int q = lane & 3, r = lane >> 2;
    const int qr = wid * 16;              // warp's q-row base within tile

    const size_t bh = (size_t)(b * H_ + h);
    const float* qptr  = g_q + (bh * T_ + (size_t)qb * 128) * D_;
    const float* kbase = g_k + bh * T_ * D_;
    const float* vbase = g_v + bh * T_ * D_;
    const int*   mbase = mask + (size_t)b * T_;

    // Stage Q (128 x 64) as tf32
#pragma unroll
    for (int i = 0; i < 8; ++i) {
        int f = tid + i * 256;
        int row = f >> 4, c4 = (f & 15) << 2;
        float4 v = *(const float4*)(qptr + (size_t)row * D_ + c4);
        uint4 u = {f2tf(v.x), f2tf(v.y), f2tf(v.z), f2tf(v.w)};
        *(uint4*)&Qs[row * QS_STRIDE + c4] = u;
    }
    __syncthreads();

    // Q fragments: register-resident for all 32 K-blocks
    uint32_t qf[8][4];
    const int a_row = qr + (lane & 15);
    const int a_col = (lane >> 4) << 2;
#pragma unroll
    for (int ks = 0; ks < 8; ++ks)
        ldsm4(qf[ks][0], qf[ks][1], qf[ks][2], qf[ks][3],
              sptr(&Qs[a_row * QS_STRIDE + ks * 8 + a_col]));

    float oacc[8][4];
#pragma unroll
    for (int i = 0; i < 8; ++i)
#pragma unroll
        for (int j = 0; j < 4; ++j) oacc[i][j] = 0.f;
    float m0 = -1e30f, m1 = -1e30f, l0 = 0.f, l1 = 0.f;
    const float scale = 0.125f;

    const int b_row = (lane & 7) + ((lane & 16) ? 8 : 0);
    const int b_col = (lane & 8) ? 4 : 0;

    for (int kb = 0; kb < T_ / 64; ++kb) {
        const float* kptr = kbase + (size_t)kb * 64 * D_;
        const float* vptr = vbase + (size_t)kb * 64 * D_;
        // Stage K [krow][d] and V transposed [d][krow], cvt tf32
#pragma unroll
        for (int i = 0; i < 4; ++i) {
            int f = tid + i * 256;
            int row = f >> 4, c4 = (f & 15) << 2;
            float4 v = *(const float4*)(kptr + (size_t)row * D_ + c4);
            uint4 u = {f2tf(v.x), f2tf(v.y), f2tf(v.z), f2tf(v.w)};
            *(uint4*)&Ks[row * QS_STRIDE + c4] = u;
        }
#pragma unroll
        for (int i = 0; i < 4; ++i) {
            int f = tid + i * 256;
            int row = f >> 4, c4 = (f & 15) << 2;
            float4 v = *(const float4*)(vptr + (size_t)row * D_ + c4);
            Vt[(c4 + 0) * QS_STRIDE + row] = __uint_as_float(f2tf(v.x));
            Vt[(c4 + 1) * QS_STRIDE + row] = __uint_as_float(f2tf(v.y));
            Vt[(c4 + 2) * QS_STRIDE + row] = __uint_as_float(f2tf(v.z));
            Vt[(c4 + 3) * QS_STRIDE + row] = __uint_as_float(f2tf(v.w));
        }
        if (tid < 64) mk[tid] = mbase[kb * 64 + tid];
        __syncthreads();

        // S = Q . K^T (warp: 16 x 64)
        float sacc[8][4];
#pragma unroll
        for (int i = 0; i < 8; ++i)
#pragma unroll
            for (int j = 0; j < 4; ++j) sacc[i][j] = 0.f;

#pragma unroll
        for (int ks = 0; ks < 8; ++ks) {
            uint32_t kf[8][2];
#pragma unroll
            for (int np = 0; np < 4; ++np) {
                uint32_t r0, r1, r2, r3;
                ldsm4(r0, r1, r2, r3,
                      sptr(&Ks[(np * 16 + b_row) * QS_STRIDE + ks * 8 + b_col]));
                kf[np * 2][0] = r0;     kf[np * 2][1] = r1;
                kf[np * 2 + 1][0] = r2; kf[np * 2 + 1][1] = r3;
            }
#pragma unroll
            for (int nt = 0; nt < 8; ++nt)
                mma_tf32(sacc[nt], qf[ks], kf[nt]);
        }

        // mask + scale, row max (rows r and r+8 of this warp's 16)
        float rm0 = -1e30f, rm1 = -1e30f;
#pragma unroll
        for (int nt = 0; nt < 8; ++nt) {
            int c = nt * 8 + 2 * q;
            bool ma = mk[c] != 0, mb = mk[c + 1] != 0;
            sacc[nt][0] = ma ? sacc[nt][0] * scale : -1e30f;
            sacc[nt][1] = mb ? sacc[nt][1] * scale : -1e30f;
            sacc[nt][2] = ma ? sacc[nt][2] * scale : -1e30f;
            sacc[nt][3] = mb ? sacc[nt][3] * scale : -1e30f;
            rm0 = fmaxf(rm0, fmaxf(sacc[nt][0], sacc[nt][1]));
            rm1 = fmaxf(rm1, fmaxf(sacc[nt][2], sacc[nt][3]));
        }
#pragma unroll
        for (int st = 1; st < 4; st <<= 1) {
            rm0 = fmaxf(rm0, __shfl_xor_sync(0xffffffffu, rm0, st));
            rm1 = fmaxf(rm1, __shfl_xor_sync(0xffffffffu, rm1, st));
        }
        float mn0 = fmaxf(m0, rm0), mn1 = fmaxf(m1, rm1);
        float cr0 = __expf(m0 - mn0), cr1 = __expf(m1 - mn1);
        m0 = mn0; m1 = mn1;

        float rs0 = 0.f, rs1 = 0.f;
#pragma unroll
        for (int nt = 0; nt < 8; ++nt) {
            float e0 = __expf(sacc[nt][0] - mn0);
            float e1 = __expf(sacc[nt][1] - mn0);
            float e2 = __expf(sacc[nt][2] - mn1);
            float e3 = __expf(sacc[nt][3] - mn1);
            rs0 += e0 + e1; rs1 += e2 + e3;
            uint2 p01 = {f2tf(e0), f2tf(e1)};
            uint2 p23 = {f2tf(e2), f2tf(e3)};
            *(uint2*)&Ps[(qr + r) * QS_STRIDE + nt * 8 + 2 * q] = p01;
            *(uint2*)&Ps[(qr + r + 8) * QS_STRIDE + nt * 8 + 2 * q] = p23;
        }
#pragma unroll
        for (int st = 1; st < 4; st <<= 1) {
            rs0 += __shfl_xor_sync(0xffffffffu, rs0, st);
            rs1 += __shfl_xor_sync(0xffffffffu, rs1, st);
        }
        l0 = l0 * cr0 + rs0;
        l1 = l1 * cr1 + rs1;
#pragma unroll
        for (int nt = 0; nt < 8; ++nt) {
            oacc[nt][0] *= cr0; oacc[nt][1] *= cr0;
            oacc[nt][2] *= cr1; oacc[nt][3] *= cr1;
        }
        __syncwarp();

        // O += P . V (warp rows only; P read back as A-fragments)
#pragma unroll
        for (int ks = 0; ks < 8; ++ks) {
            uint32_t pf[4];
            ldsm4(pf[0], pf[1], pf[2], pf[3],
                  sptr(&Ps[a_row * QS_STRIDE + ks * 8 + a_col]));
            uint32_t vf[8][2];
#pragma unroll
            for (int np = 0; np < 4; ++np) {
                uint32_t r0, r1, r2, r3;
                ldsm4(r0, r1, r2, r3,
                      sptr(&Vt[(np * 16 + b_row) * QS_STRIDE + ks * 8 + b_col]));
                vf[np * 2][0] = r0;     vf[np * 2][1] = r1;
                vf[np * 2 + 1][0] = r2; vf[np * 2 + 1][1] = r3;
            }
#pragma unroll
            for (int nt = 0; nt < 8; ++nt)
                mma_tf32(oacc[nt], pf, vf[nt]);
        }
        __syncthreads();
    }

    // Normalize + write. out = b*T*C + h*T*D + t*D + d
    float inv0 = (l0 > 0.f) ? 1.f / l0 : 0.f;
    float inv1 = (l1 > 0.f) ? 1.f / l1 : 0.f;
    float* obase = out + (size_t)b * T_ * C_ + (size_t)h * T_ * D_;
    int row0 = qb * 128 + qr + r;
#pragma unroll
    for (int nt = 0; nt < 8; ++nt) {
        int dd = nt * 8 + 2 * q;
        float2 v0 = {oacc[nt][0] * inv0, oacc[nt][1] * inv0};
        float2 v1 = {oacc[nt][2] * inv1, oacc[nt][3] * inv1};
        *(float2*)(obase + (size_t)row0 * D_ + dd) = v0;
        *(float2*)(obase + (size_t)(row0 + 8) * D_ + dd) = v1;
    }
}

// ---------------------------------------------------------------------------
extern "C" void kernel_launch(void* const* d_in, const int* in_sizes, int n_in,
                              void* d_out, int out_size) {
    (void)in_sizes; (void)n_in; (void)out_size;
    const float* x    = (const float*)d_in[0];
    const int*   mask = (const int*)d_in[1];
    const float* W    = (const float*)d_in[2];
    const float* bias = (const float*)d_in[3];
    float*       out  = (float*)d_out;

    static int _attr_once = []() {
        cudaFuncSetAttribute(attn_kernel,
                             cudaFuncAttributeMaxDynamicSharedMemorySize,
                             AT_SMEM_BYTES);
        return 0;
    }();
    (void)_attr_once;

    dim3 g1(TC3 / 128, M_ / 128);   // (24, 128)
    qkv_gemm_kernel<<<g1, 256>>>(x, W, bias);

    dim3 g2(T_ / 128, H_, B_);      // (16, 16, 8)
    attn_kernel<<<g2, 256, AT_SMEM_BYTES>>>(mask, out);
}

// round 5
// speedup vs baseline: 1.7325x; 1.7325x over previous
#include <cuda_runtime.h>
#include <cuda_fp16.h>
#include <cstdint>

static constexpr int B_  = 8;
static constexpr int T_  = 2048;
static constexpr int C_  = 1024;
static constexpr int H_  = 16;
static constexpr int D_  = 64;
static constexpr int TC3 = 3 * C_;
static constexpr int M_  = B_ * T_;

// Scratch q,k,v in (B,H,T,D) layout, fp16
__device__ __half g_q[(size_t)B_ * H_ * T_ * D_];
__device__ __half g_k[(size_t)B_ * H_ * T_ * D_];
__device__ __half g_v[(size_t)B_ * H_ * T_ * D_];

// ---------------------------------------------------------------------------
__device__ __forceinline__ uint32_t sptr(const void* p) {
    return (uint32_t)__cvta_generic_to_shared(p);
}
__device__ __forceinline__ void ldsm4(uint32_t& r0, uint32_t& r1,
                                      uint32_t& r2, uint32_t& r3, uint32_t a) {
    asm volatile("ldmatrix.sync.aligned.m8n8.x4.shared.b16 {%0,%1,%2,%3}, [%4];"
                 : "=r"(r0), "=r"(r1), "=r"(r2), "=r"(r3) : "r"(a));
}
// D(16x8,f32) += A(16x16,f16) * B(16x8,f16)^T-stored
__device__ __forceinline__ void mma_f16(float* d, const uint32_t* a,
                                        const uint32_t* b) {
    asm volatile(
        "mma.sync.aligned.m16n8k16.row.col.f32.f16.f16.f32 "
        "{%0,%1,%2,%3}, {%4,%5,%6,%7}, {%8,%9}, {%0,%1,%2,%3};"
        : "+f"(d[0]), "+f"(d[1]), "+f"(d[2]), "+f"(d[3])
        : "r"(a[0]), "r"(a[1]), "r"(a[2]), "r"(a[3]), "r"(b[0]), "r"(b[1]));
}

// ---------------------------------------------------------------------------
// Kernel 1: qkv = x @ W + b (fp16 mma, fp32 accum), scatter (B,H,T,D) fp16.
// 128x128 tile, BK=32, 8 warps (2Mx4N), warp tile 64x32.
// ---------------------------------------------------------------------------
__global__ __launch_bounds__(256, 2) void qkv_gemm_kernel(
    const float* __restrict__ x, const float* __restrict__ W,
    const float* __restrict__ bias)
{
    __shared__ __align__(16) __half As[128 * 40];  // [m][k] stride 40 (80B, 16B-mult)
    __shared__ __align__(16) __half Bt[128 * 40];  // [n][k] stride 40

    const int bm = blockIdx.y, bn = blockIdx.x;
    const int tid = threadIdx.x;
    const int wid = tid >> 5, lane = tid & 31;
    const int wm = wid >> 2, wn = wid & 3;
    const int q = lane & 3, r = lane >> 2;

    float acc[4][4][4];
#pragma unroll
    for (int i = 0; i < 4; ++i)
#pragma unroll
        for (int j = 0; j < 4; ++j)
#pragma unroll
            for (int k = 0; k < 4; ++k) acc[i][j][k] = 0.f;

    const int a_row = wm * 64 + (lane & 15);
    const int a_col = (lane >> 4) * 8;                      // halves
    const int b_row = wn * 32 + (lane & 7) + ((lane & 16) ? 8 : 0);
    const int b_col = (lane & 8) ? 8 : 0;                   // halves

    for (int k0 = 0; k0 < C_; k0 += 32) {
        // Stage A (128 x 32 fp32 -> fp16)
#pragma unroll
        for (int i = 0; i < 4; ++i) {
            int f = tid + i * 256;
            int row = f >> 3, c4 = (f & 7) << 2;
            float4 v = *(const float4*)(x + (size_t)(bm * 128 + row) * C_ + k0 + c4);
            __half2* d = (__half2*)&As[row * 40 + c4];
            d[0] = __floats2half2_rn(v.x, v.y);
            d[1] = __floats2half2_rn(v.z, v.w);
        }
        // Stage B (32 x 128 fp32) transposed to [n][k] fp16
#pragma unroll
        for (int i = 0; i < 4; ++i) {
            int f = tid + i * 256;
            int kr = f >> 5, c4 = (f & 31) << 2;
            float4 v = *(const float4*)(W + (size_t)(k0 + kr) * TC3 + bn * 128 + c4);
            Bt[(c4 + 0) * 40 + kr] = __float2half_rn(v.x);
            Bt[(c4 + 1) * 40 + kr] = __float2half_rn(v.y);
            Bt[(c4 + 2) * 40 + kr] = __float2half_rn(v.z);
            Bt[(c4 + 3) * 40 + kr] = __float2half_rn(v.w);
        }
        __syncthreads();

#pragma unroll
        for (int ks = 0; ks < 2; ++ks) {
            uint32_t af[4][4];
#pragma unroll
            for (int mt = 0; mt < 4; ++mt)
                ldsm4(af[mt][0], af[mt][1], af[mt][2], af[mt][3],
                      sptr(&As[(a_row + mt * 16) * 40 + ks * 16 + a_col]));
            uint32_t bf[4][2];
#pragma unroll
            for (int np = 0; np < 2; ++np) {
                uint32_t r0, r1, r2, r3;
                ldsm4(r0, r1, r2, r3,
                      sptr(&Bt[(b_row + np * 16) * 40 + ks * 16 + b_col]));
                bf[np * 2][0] = r0;     bf[np * 2][1] = r1;
                bf[np * 2 + 1][0] = r2; bf[np * 2 + 1][1] = r3;
            }
#pragma unroll
            for (int mt = 0; mt < 4; ++mt)
#pragma unroll
                for (int nt = 0; nt < 4; ++nt)
                    mma_f16(acc[mt][nt], af[mt], bf[nt]);
        }
        __syncthreads();
    }

    // Epilogue: bias + scatter as fp16
    const int which = bn >> 3;                   // 128-col blocks, 8 per 1024
    __half* dst = (which == 0) ? g_q : (which == 1) ? g_k : g_v;
#pragma unroll
    for (int mt = 0; mt < 4; ++mt) {
#pragma unroll
        for (int half_ = 0; half_ < 2; ++half_) {
            int m = bm * 128 + wm * 64 + mt * 16 + r + half_ * 8;
            int bb = m >> 11, tt = m & 2047;
#pragma unroll
            for (int nt = 0; nt < 4; ++nt) {
                int n = bn * 128 + wn * 32 + nt * 8 + 2 * q;
                int cc = n & 1023;
                int hh = cc >> 6, dd = cc & 63;
                float2 bv = *(const float2*)(bias + n);
                __half2 o = __floats2half2_rn(acc[mt][nt][half_ * 2 + 0] + bv.x,
                                              acc[mt][nt][half_ * 2 + 1] + bv.y);
                *(__half2*)(dst + ((size_t)(bb * H_ + hh) * T_ + tt) * D_ + dd) = o;
            }
        }
    }
}

// ---------------------------------------------------------------------------
// Kernel 2: flash attention, fp16 mma. CTA = (b,h,128 q-rows), 8 warps,
// warp = 16 q-rows. Online softmax over 64-key blocks.
// ---------------------------------------------------------------------------
__global__ __launch_bounds__(256, 2) void attn_kernel(
    const int* __restrict__ mask, float* __restrict__ out)
{
    __shared__ __align__(16) __half Qs[128 * 72];  // aliased as Ps after frag load
    __shared__ __align__(16) __half Ks[64 * 72];   // [krow][d]
    __shared__ __align__(16) __half Vt[64 * 72];   // [d][krow]
    __shared__ int mk[64];
    __half* Ps = Qs;

    const int qb = blockIdx.x, h = blockIdx.y, b = blockIdx.z;
    const int tid = threadIdx.x;
    const int wid = tid >> 5, lane = tid & 31;
    const int q = lane & 3, r = lane >> 2;
    const int qr = wid * 16;

    const size_t bh = (size_t)(b * H_ + h);
    const __half* qptr  = g_q + (bh * T_ + (size_t)qb * 128) * D_;
    const __half* kbase = g_k + bh * T_ * D_;
    const __half* vbase = g_v + bh * T_ * D_;
    const int*    mbase = mask + (size_t)b * T_;

    // Stage Q (128 x 64 halves), plain copy
#pragma unroll
    for (int i = 0; i < 4; ++i) {
        int f = tid + i * 256;
        int row = f >> 3, c8 = (f & 7) << 3;
        *(uint4*)&Qs[row * 72 + c8] = *(const uint4*)(qptr + (size_t)row * D_ + c8);
    }
    __syncthreads();

    // Q fragments, register-resident for all K-blocks: 4 k-steps of 16
    uint32_t qf[4][4];
    const int a_row = qr + (lane & 15);
    const int a_col = (lane >> 4) * 8;
#pragma unroll
    for (int ks = 0; ks < 4; ++ks)
        ldsm4(qf[ks][0], qf[ks][1], qf[ks][2], qf[ks][3],
              sptr(&Qs[a_row * 72 + ks * 16 + a_col]));

    float oacc[8][4];
#pragma unroll
    for (int i = 0; i < 8; ++i)
#pragma unroll
        for (int j = 0; j < 4; ++j) oacc[i][j] = 0.f;
    float m0 = -1e30f, m1 = -1e30f, l0 = 0.f, l1 = 0.f;
    const float scale = 0.125f;

    const int b_row = (lane & 7) + ((lane & 16) ? 8 : 0);
    const int b_col = (lane & 8) ? 8 : 0;

    for (int kb = 0; kb < T_ / 64; ++kb) {
        const __half* kptr = kbase + (size_t)kb * 64 * D_;
        const __half* vptr = vbase + (size_t)kb * 64 * D_;
        // K [krow][d]
#pragma unroll
        for (int i = 0; i < 2; ++i) {
            int f = tid + i * 256;
            int row = f >> 3, c8 = (f & 7) << 3;
            *(uint4*)&Ks[row * 72 + c8] = *(const uint4*)(kptr + (size_t)row * D_ + c8);
        }
        // V transposed [d][krow]
#pragma unroll
        for (int i = 0; i < 2; ++i) {
            int f = tid + i * 256;
            int row = f >> 3, c8 = (f & 7) << 3;
            uint4 u = *(const uint4*)(vptr + (size_t)row * D_ + c8);
            const __half* hv = (const __half*)&u;
#pragma unroll
            for (int j = 0; j < 8; ++j)
                Vt[(c8 + j) * 72 + row] = hv[j];
        }
        if (tid < 64) mk[tid] = mbase[kb * 64 + tid];
        __syncthreads();

        // S = Q.K^T (warp: 16 x 64)
        float sacc[8][4];
#pragma unroll
        for (int i = 0; i < 8; ++i)
#pragma unroll
            for (int j = 0; j < 4; ++j) sacc[i][j] = 0.f;

#pragma unroll
        for (int ks = 0; ks < 4; ++ks) {
            uint32_t kf[8][2];
#pragma unroll
            for (int np = 0; np < 4; ++np) {
                uint32_t r0, r1, r2, r3;
                ldsm4(r0, r1, r2, r3,
                      sptr(&Ks[(np * 16 + b_row) * 72 + ks * 16 + b_col]));
                kf[np * 2][0] = r0;     kf[np * 2][1] = r1;
                kf[np * 2 + 1][0] = r2; kf[np * 2 + 1][1] = r3;
            }
#pragma unroll
            for (int nt = 0; nt < 8; ++nt)
                mma_f16(sacc[nt], qf[ks], kf[nt]);
        }

        // mask + scale + row max (rows r, r+8)
        float rm0 = -1e30f, rm1 = -1e30f;
#pragma unroll
        for (int nt = 0; nt < 8; ++nt) {
            int c = nt * 8 + 2 * q;
            bool ma = mk[c] != 0, mb = mk[c + 1] != 0;
            sacc[nt][0] = ma ? sacc[nt][0] * scale : -1e30f;
            sacc[nt][1] = mb ? sacc[nt][1] * scale : -1e30f;
            sacc[nt][2] = ma ? sacc[nt][2] * scale : -1e30f;
            sacc[nt][3] = mb ? sacc[nt][3] * scale : -1e30f;
            rm0 = fmaxf(rm0, fmaxf(sacc[nt][0], sacc[nt][1]));
            rm1 = fmaxf(rm1, fmaxf(sacc[nt][2], sacc[nt][3]));
        }
#pragma unroll
        for (int st = 1; st < 4; st <<= 1) {
            rm0 = fmaxf(rm0, __shfl_xor_sync(0xffffffffu, rm0, st));
            rm1 = fmaxf(rm1, __shfl_xor_sync(0xffffffffu, rm1, st));
        }
        float mn0 = fmaxf(m0, rm0), mn1 = fmaxf(m1, rm1);
        float cr0 = __expf(m0 - mn0), cr1 = __expf(m1 - mn1);
        m0 = mn0; m1 = mn1;

        float rs0 = 0.f, rs1 = 0.f;
#pragma unroll
        for (int nt = 0; nt < 8; ++nt) {
            float e0 = __expf(sacc[nt][0] - mn0);
            float e1 = __expf(sacc[nt][1] - mn0);
            float e2 = __expf(sacc[nt][2] - mn1);
            float e3 = __expf(sacc[nt][3] - mn1);
            __half2 p01 = __floats2half2_rn(e0, e1);
            __half2 p23 = __floats2half2_rn(e2, e3);
            rs0 += __low2float(p01) + __high2float(p01);
            rs1 += __low2float(p23) + __high2float(p23);
            *(__half2*)&Ps[(qr + r) * 72 + nt * 8 + 2 * q] = p01;
            *(__half2*)&Ps[(qr + r + 8) * 72 + nt * 8 + 2 * q] = p23;
        }
#pragma unroll
        for (int st = 1; st < 4; st <<= 1) {
            rs0 += __shfl_xor_sync(0xffffffffu, rs0, st);
            rs1 += __shfl_xor_sync(0xffffffffu, rs1, st);
        }
        l0 = l0 * cr0 + rs0;
        l1 = l1 * cr1 + rs1;
#pragma unroll
        for (int nt = 0; nt < 8; ++nt) {
            oacc[nt][0] *= cr0; oacc[nt][1] *= cr0;
            oacc[nt][2] *= cr1; oacc[nt][3] *= cr1;
        }
        __syncwarp();

        // O += P.V (warp rows only)
#pragma unroll
        for (int ks = 0; ks < 4; ++ks) {
            uint32_t pf[4];
            ldsm4(pf[0], pf[1], pf[2], pf[3],
                  sptr(&Ps[a_row * 72 + ks * 16 + a_col]));
            uint32_t vf[8][2];
#pragma unroll
            for (int np = 0; np < 4; ++np) {
                uint32_t r0, r1, r2, r3;
                ldsm4(r0, r1, r2, r3,
                      sptr(&Vt[(np * 16 + b_row) * 72 + ks * 16 + b_col]));
                vf[np * 2][0] = r0;     vf[np * 2][1] = r1;
                vf[np * 2 + 1][0] = r2; vf[np * 2 + 1][1] = r3;
            }
#pragma unroll
            for (int nt = 0; nt < 8; ++nt)
                mma_f16(oacc[nt], pf, vf[nt]);
        }
        __syncthreads();
    }

    // Normalize + write fp32. out = b*T*C + h*T*D + t*D + d
    float inv0 = (l0 > 0.f) ? 1.f / l0 : 0.f;
    float inv1 = (l1 > 0.f) ? 1.f / l1 : 0.f;
    float* obase = out + (size_t)b * T_ * C_ + (size_t)h * T_ * D_;
    int row0 = qb * 128 + qr + r;
#pragma unroll
    for (int nt = 0; nt < 8; ++nt) {
        int dd = nt * 8 + 2 * q;
        float2 v0 = {oacc[nt][0] * inv0, oacc[nt][1] * inv0};
        float2 v1 = {oacc[nt][2] * inv1, oacc[nt][3] * inv1};
        *(float2*)(obase + (size_t)row0 * D_ + dd) = v0;
        *(float2*)(obase + (size_t)(row0 + 8) * D_ + dd) = v1;
    }
}

// ---------------------------------------------------------------------------
extern "C" void kernel_launch(void* const* d_in, const int* in_sizes, int n_in,
                              void* d_out, int out_size) {
    (void)in_sizes; (void)n_in; (void)out_size;
    const float* x    = (const float*)d_in[0];
    const int*   mask = (const int*)d_in[1];
    const float* W    = (const float*)d_in[2];
    const float* bias = (const float*)d_in[3];
    float*       out  = (float*)d_out;

    dim3 g1(TC3 / 128, M_ / 128);   // (24, 128)
    qkv_gemm_kernel<<<g1, 256>>>(x, W, bias);

    dim3 g2(T_ / 128, H_, B_);      // (16, 16, 8)
    attn_kernel<<<g2, 256>>>(mask, out);
}

// round 7
// speedup vs baseline: 4.4070x; 2.5438x over previous
#include <cuda_runtime.h>
#include <cuda_fp16.h>
#include <cstdint>

static constexpr int B_  = 8;
static constexpr int T_  = 2048;
static constexpr int C_  = 1024;
static constexpr int H_  = 16;
static constexpr int D_  = 64;
static constexpr int TC3 = 3 * C_;
static constexpr int M_  = B_ * T_;

// Device scratch
__device__ __half g_xh[(size_t)M_ * C_];          // x in fp16
__device__ __half g_wh[(size_t)C_ * TC3];         // W in fp16
__device__ __half g_q[(size_t)B_ * H_ * T_ * D_];
__device__ __half g_k[(size_t)B_ * H_ * T_ * D_];
__device__ __half g_v[(size_t)B_ * H_ * T_ * D_];

// Dynamic smem sizes
static constexpr int G_SMEM = (3 * 128 * 40 + 3 * 32 * 136) * 2;           // 56832 B
static constexpr int A_SMEM = (128 * 72 + 2 * 64 * 72 + 2 * 64 * 72) * 2
                              + 2 * 64 * 4;                                 // 55808 B

// ---------------------------------------------------------------------------
__device__ __forceinline__ uint32_t sptr(const void* p) {
    return (uint32_t)__cvta_generic_to_shared(p);
}
__device__ __forceinline__ void ldsm4(uint32_t& r0, uint32_t& r1,
                                      uint32_t& r2, uint32_t& r3, uint32_t a) {
    asm volatile("ldmatrix.sync.aligned.m8n8.x4.shared.b16 {%0,%1,%2,%3}, [%4];"
                 : "=r"(r0), "=r"(r1), "=r"(r2), "=r"(r3) : "r"(a));
}
__device__ __forceinline__ void ldsm4t(uint32_t& r0, uint32_t& r1,
                                       uint32_t& r2, uint32_t& r3, uint32_t a) {
    asm volatile("ldmatrix.sync.aligned.m8n8.x4.trans.shared.b16 {%0,%1,%2,%3}, [%4];"
                 : "=r"(r0), "=r"(r1), "=r"(r2), "=r"(r3) : "r"(a));
}
__device__ __forceinline__ void mma_f16(float* d, const uint32_t* a,
                                        const uint32_t* b) {
    asm volatile(
        "mma.sync.aligned.m16n8k16.row.col.f32.f16.f16.f32 "
        "{%0,%1,%2,%3}, {%4,%5,%6,%7}, {%8,%9}, {%0,%1,%2,%3};"
        : "+f"(d[0]), "+f"(d[1]), "+f"(d[2]), "+f"(d[3])
        : "r"(a[0]), "r"(a[1]), "r"(a[2]), "r"(a[3]), "r"(b[0]), "r"(b[1]));
}
__device__ __forceinline__ void cpa16(uint32_t dst, const void* src) {
    asm volatile("cp.async.cg.shared.global [%0], [%1], 16;" :: "r"(dst), "l"(src));
}
__device__ __forceinline__ void cpa4(uint32_t dst, const void* src) {
    asm volatile("cp.async.ca.shared.global [%0], [%1], 4;" :: "r"(dst), "l"(src));
}
__device__ __forceinline__ void cp_commit() {
    asm volatile("cp.async.commit_group;" ::: "memory");
}
template <int N>
__device__ __forceinline__ void cp_wait() {
    asm volatile("cp.async.wait_group %0;" :: "n"(N) : "memory");
}

// ---------------------------------------------------------------------------
// Kernel 0: fp32 -> fp16 convert (vectorized)
// ---------------------------------------------------------------------------
__global__ __launch_bounds__(256) void cvt_kernel(
    const float4* __restrict__ src, __half2* __restrict__ dst, int n4)
{
    int i = blockIdx.x * blockDim.x + threadIdx.x;
    if (i < n4) {
        float4 v = src[i];
        dst[2 * i + 0] = __floats2half2_rn(v.x, v.y);
        dst[2 * i + 1] = __floats2half2_rn(v.z, v.w);
    }
}

// ---------------------------------------------------------------------------
// Kernel 1: qkv = xh @ wh + b. 128x128 tile, BK=32, 3-stage cp.async pipeline.
// 8 warps (2Mx4N), warp tile 64x32. B frags via ldmatrix.trans.
// ---------------------------------------------------------------------------
__global__ __launch_bounds__(256, 2) void qkv_gemm_kernel(
    const float* __restrict__ bias)
{
    extern __shared__ __align__(16) __half gsm[];
    __half* AsB = gsm;                    // 3 stages of [128][40]
    __half* BsB = gsm + 3 * 128 * 40;     // 3 stages of [32][136]

    const int bm = blockIdx.y, bn = blockIdx.x;
    const int tid = threadIdx.x;
    const int wid = tid >> 5, lane = tid & 31;
    const int wm = wid >> 2, wn = wid & 3;
    const int q = lane & 3, r = lane >> 2;

    auto stage = [&](int s, int k0) {
        __half* As = AsB + s * 128 * 40;
        __half* Bs = BsB + s * 32 * 136;
#pragma unroll
        for (int i = 0; i < 2; ++i) {
            int f = tid + i * 256;                 // 0..511
            int row = f >> 2, c8 = (f & 3) << 3;   // A: 128 x 32
            cpa16(sptr(&As[row * 40 + c8]),
                  g_xh + (size_t)(bm * 128 + row) * C_ + k0 + c8);
            int kr = f >> 4, n8 = (f & 15) << 3;   // B: 32 x 128
            cpa16(sptr(&Bs[kr * 136 + n8]),
                  g_wh + (size_t)(k0 + kr) * TC3 + bn * 128 + n8);
        }
    };

    float acc[4][4][4];
#pragma unroll
    for (int i = 0; i < 4; ++i)
#pragma unroll
        for (int j = 0; j < 4; ++j)
#pragma unroll
            for (int k = 0; k < 4; ++k) acc[i][j][k] = 0.f;

    stage(0, 0);  cp_commit();
    stage(1, 32); cp_commit();

    const int a_row = wm * 64 + (lane & 15);
    const int a_col = (lane >> 4) * 8;
    const int b_rowk = lane & 15;
    const int b_coln = (lane >> 4) * 8;

    for (int kt = 0; kt < 32; ++kt) {
        cp_wait<1>();
        __syncthreads();
        if (kt < 30) stage((kt + 2) % 3, (kt + 2) * 32);
        cp_commit();

        const __half* A  = AsB + (kt % 3) * 128 * 40;
        const __half* Bm = BsB + (kt % 3) * 32 * 136;
#pragma unroll
        for (int ks = 0; ks < 2; ++ks) {
            uint32_t af[4][4];
#pragma unroll
            for (int mt = 0; mt < 4; ++mt)
                ldsm4(af[mt][0], af[mt][1], af[mt][2], af[mt][3],
                      sptr(&A[(a_row + mt * 16) * 40 + ks * 16 + a_col]));
            uint32_t bf[4][2];
#pragma unroll
            for (int np = 0; np < 2; ++np) {
                uint32_t r0, r1, r2, r3;
                ldsm4t(r0, r1, r2, r3,
                       sptr(&Bm[(ks * 16 + b_rowk) * 136 + wn * 32 + np * 16 + b_coln]));
                bf[np * 2][0] = r0;     bf[np * 2][1] = r1;
                bf[np * 2 + 1][0] = r2; bf[np * 2 + 1][1] = r3;
            }
#pragma unroll
            for (int mt = 0; mt < 4; ++mt)
#pragma unroll
                for (int nt = 0; nt < 4; ++nt)
                    mma_f16(acc[mt][nt], af[mt], bf[nt]);
        }
    }

    // Epilogue: bias + scatter fp16 into (B,H,T,D)
    const int which = bn >> 3;
    __half* dst = (which == 0) ? g_q : (which == 1) ? g_k : g_v;
#pragma unroll
    for (int mt = 0; mt < 4; ++mt) {
#pragma unroll
        for (int hf = 0; hf < 2; ++hf) {
            int m = bm * 128 + wm * 64 + mt * 16 + r + hf * 8;
            int bb = m >> 11, tt = m & 2047;
#pragma unroll
            for (int nt = 0; nt < 4; ++nt) {
                int n = bn * 128 + wn * 32 + nt * 8 + 2 * q;
                int cc = n & 1023;
                int hh = cc >> 6, dd = cc & 63;
                float2 bv = *(const float2*)(bias + n);
                __half2 o = __floats2half2_rn(acc[mt][nt][hf * 2 + 0] + bv.x,
                                              acc[mt][nt][hf * 2 + 1] + bv.y);
                *(__half2*)(dst + ((size_t)(bb * H_ + hh) * T_ + tt) * D_ + dd) = o;
            }
        }
    }
}

// ---------------------------------------------------------------------------
// Kernel 2: flash attention. 8 warps x 16 q-rows. Fixed-base softmax.
// P kept in registers (C-frag == A-frag layout). V frags via ldmatrix.trans.
// K/V double-buffered with cp.async.
// ---------------------------------------------------------------------------
__global__ __launch_bounds__(256, 2) void attn_kernel(
    const int* __restrict__ mask, float* __restrict__ out)
{
    extern __shared__ __align__(16) __half asmem[];
    __half* Qs = asmem;                          // [128][72]
    __half* KsB = Qs + 128 * 72;                 // 2 x [64][72]
    __half* VsB = KsB + 2 * 64 * 72;             // 2 x [64][72]
    int* mkB = (int*)(VsB + 2 * 64 * 72);        // 2 x [64]

    const int qb = blockIdx.x, h = blockIdx.y, b = blockIdx.z;
    const int tid = threadIdx.x;
    const int wid = tid >> 5, lane = tid & 31;
    const int q = lane & 3, r = lane >> 2;
    const int qr = wid * 16;

    const size_t bh = (size_t)(b * H_ + h);
    const __half* qptr  = g_q + (bh * T_ + (size_t)qb * 128) * D_;
    const __half* kbase = g_k + bh * T_ * D_;
    const __half* vbase = g_v + bh * T_ * D_;
    const int*    mbase = mask + (size_t)b * T_;

    auto stage = [&](int buf, int kb) {
        const __half* kp = kbase + (size_t)kb * 64 * D_;
        const __half* vp = vbase + (size_t)kb * 64 * D_;
        __half* Ks = KsB + buf * 64 * 72;
        __half* Vs = VsB + buf * 64 * 72;
#pragma unroll
        for (int i = 0; i < 2; ++i) {
            int f = tid + i * 256;                 // 0..511
            int row = f >> 3, c8 = (f & 7) << 3;
            cpa16(sptr(&Ks[row * 72 + c8]), kp + (size_t)row * D_ + c8);
            cpa16(sptr(&Vs[row * 72 + c8]), vp + (size_t)row * D_ + c8);
        }
        if (tid < 64) cpa4(sptr(&mkB[buf * 64 + tid]), mbase + kb * 64 + tid);
    };

    stage(0, 0);
    cp_commit();

    // Stage Q, then load register-resident A fragments
#pragma unroll
    for (int i = 0; i < 4; ++i) {
        int f = tid + i * 256;
        int row = f >> 3, c8 = (f & 7) << 3;
        *(uint4*)&Qs[row * 72 + c8] = *(const uint4*)(qptr + (size_t)row * D_ + c8);
    }
    __syncthreads();

    uint32_t qf[4][4];
    const int a_row = qr + (lane & 15);
    const int a_col = (lane >> 4) * 8;
#pragma unroll
    for (int ks = 0; ks < 4; ++ks)
        ldsm4(qf[ks][0], qf[ks][1], qf[ks][2], qf[ks][3],
              sptr(&Qs[a_row * 72 + ks * 16 + a_col]));

    float oacc[8][4];
#pragma unroll
    for (int i = 0; i < 8; ++i)
#pragma unroll
        for (int j = 0; j < 4; ++j) oacc[i][j] = 0.f;
    float l0 = 0.f, l1 = 0.f;
    const float scale = 0.125f;

    const int b_row = (lane & 7) + ((lane & 16) ? 8 : 0);
    const int b_col = (lane & 8) ? 8 : 0;
    const int t_row = lane & 15;            // for ldsm.trans
    const int t_col = (lane >> 4) * 8;

    for (int kb = 0; kb < 32; ++kb) {
        const int buf = kb & 1;
        const __half* Ks = KsB + buf * 64 * 72;
        const __half* Vs = VsB + buf * 64 * 72;
        const int* mk = mkB + buf * 64;
        cp_wait<0>();
        __syncthreads();
        if (kb + 1 < 32) stage(buf ^ 1, kb + 1);
        cp_commit();

        // ---- S = Q.K^T (warp: 16 x 64) ----
        float sacc[8][4];
#pragma unroll
        for (int i = 0; i < 8; ++i)
#pragma unroll
            for (int j = 0; j < 4; ++j) sacc[i][j] = 0.f;
#pragma unroll
        for (int ks = 0; ks < 4; ++ks) {
            uint32_t kf[8][2];
#pragma unroll
            for (int np = 0; np < 4; ++np) {
                uint32_t r0, r1, r2, r3;
                ldsm4(r0, r1, r2, r3,
                      sptr(&Ks[(np * 16 + b_row) * 72 + ks * 16 + b_col]));
                kf[np * 2][0] = r0;     kf[np * 2][1] = r1;
                kf[np * 2 + 1][0] = r2; kf[np * 2 + 1][1] = r3;
            }
#pragma unroll
            for (int nt = 0; nt < 8; ++nt)
                mma_f16(sacc[nt], qf[ks], kf[nt]);
        }

        // ---- softmax (fixed base) + pack P directly into A-fragments ----
        uint32_t pf[4][4];
#pragma unroll
        for (int nt = 0; nt < 8; ++nt) {
            int c = nt * 8 + 2 * q;
            float ma = mk[c] ? 1.f : 0.f;
            float mb = mk[c + 1] ? 1.f : 0.f;
            float e0 = __expf(sacc[nt][0] * scale) * ma;
            float e1 = __expf(sacc[nt][1] * scale) * mb;
            float e2 = __expf(sacc[nt][2] * scale) * ma;
            float e3 = __expf(sacc[nt][3] * scale) * mb;
            l0 += e0 + e1;
            l1 += e2 + e3;
            __half2 h01 = __floats2half2_rn(e0, e1);
            __half2 h23 = __floats2half2_rn(e2, e3);
            pf[nt >> 1][(nt & 1) * 2 + 0] = *(uint32_t*)&h01;
            pf[nt >> 1][(nt & 1) * 2 + 1] = *(uint32_t*)&h23;
        }

        // ---- O += P.V (V fragments via ldmatrix.trans) ----
#pragma unroll
        for (int ks2 = 0; ks2 < 4; ++ks2) {
            uint32_t vf[8][2];
#pragma unroll
            for (int np = 0; np < 4; ++np) {
                uint32_t r0, r1, r2, r3;
                ldsm4t(r0, r1, r2, r3,
                       sptr(&Vs[(ks2 * 16 + t_row) * 72 + np * 16 + t_col]));
                vf[np * 2][0] = r0;     vf[np * 2][1] = r1;
                vf[np * 2 + 1][0] = r2; vf[np * 2 + 1][1] = r3;
            }
#pragma unroll
            for (int nt = 0; nt < 8; ++nt)
                mma_f16(oacc[nt], pf[ks2], vf[nt]);
        }
    }

    // Reduce l over the 4 lanes of each row quad
#pragma unroll
    for (int st = 1; st < 4; st <<= 1) {
        l0 += __shfl_xor_sync(0xffffffffu, l0, st);
        l1 += __shfl_xor_sync(0xffffffffu, l1, st);
    }
    float inv0 = (l0 > 0.f) ? 1.f / l0 : 0.f;
    float inv1 = (l1 > 0.f) ? 1.f / l1 : 0.f;

    // Write out: index = b*T*C + h*T*D + t*D + d
    float* obase = out + (size_t)b * T_ * C_ + (size_t)h * T_ * D_;
    int row0 = qb * 128 + qr + r;
#pragma unroll
    for (int nt = 0; nt < 8; ++nt) {
        int dd = nt * 8 + 2 * q;
        float2 v0 = {oacc[nt][0] * inv0, oacc[nt][1] * inv0};
        float2 v1 = {oacc[nt][2] * inv1, oacc[nt][3] * inv1};
        *(float2*)(obase + (size_t)row0 * D_ + dd) = v0;
        *(float2*)(obase + (size_t)(row0 + 8) * D_ + dd) = v1;
    }
}

// ---------------------------------------------------------------------------
extern "C" void kernel_launch(void* const* d_in, const int* in_sizes, int n_in,
                              void* d_out, int out_size) {
    (void)in_sizes; (void)n_in; (void)out_size;
    const float* x    = (const float*)d_in[0];
    const int*   mask = (const int*)d_in[1];
    const float* W    = (const float*)d_in[2];
    const float* bias = (const float*)d_in[3];
    float*       out  = (float*)d_out;

    static __half2* xh_p = []() {
        void* p; cudaGetSymbolAddress(&p, g_xh); return (__half2*)p; }();
    static __half2* wh_p = []() {
        void* p; cudaGetSymbolAddress(&p, g_wh); return (__half2*)p; }();
    static int _once = []() {
        cudaFuncSetAttribute(qkv_gemm_kernel,
                             cudaFuncAttributeMaxDynamicSharedMemorySize, G_SMEM);
        cudaFuncSetAttribute(attn_kernel,
                             cudaFuncAttributeMaxDynamicSharedMemorySize, A_SMEM);
        return 0; }();
    (void)_once;

    int n4x = M_ * C_ / 4;
    int n4w = C_ * TC3 / 4;
    cvt_kernel<<<(n4x + 255) / 256, 256>>>((const float4*)x, xh_p, n4x);
    cvt_kernel<<<(n4w + 255) / 256, 256>>>((const float4*)W, wh_p, n4w);

    dim3 g1(TC3 / 128, M_ / 128);   // (24, 128)
    qkv_gemm_kernel<<<g1, 256, G_SMEM>>>(bias);

    dim3 g2(T_ / 128, H_, B_);      // (16, 16, 8)
    attn_kernel<<<g2, 256, A_SMEM>>>(mask, out);
}

// round 8
// speedup vs baseline: 4.8825x; 1.1079x over previous
#include <cuda_runtime.h>
#include <cuda_fp16.h>
#include <cstdint>

static constexpr int B_  = 8;
static constexpr int T_  = 2048;
static constexpr int C_  = 1024;
static constexpr int H_  = 16;
static constexpr int D_  = 64;
static constexpr int TC3 = 3 * C_;
static constexpr int M_  = B_ * T_;

// Device scratch
__device__ __half g_xh[(size_t)M_ * C_];          // x in fp16
__device__ __half g_wh[(size_t)C_ * TC3];         // W in fp16
__device__ __half g_q[(size_t)B_ * H_ * T_ * D_]; // pre-scaled by 0.125*log2(e)
__device__ __half g_k[(size_t)B_ * H_ * T_ * D_];
__device__ __half g_v[(size_t)B_ * H_ * T_ * D_]; // masked rows zeroed

// Dynamic smem sizes
static constexpr int G_SMEM = (3 * 128 * 40 + 3 * 32 * 136) * 2;            // 56832 B
static constexpr int A_SMEM = (128 * 72 + 2 * 64 * 72 + 2 * 64 * 72) * 2;   // 55296 B

// ---------------------------------------------------------------------------
__device__ __forceinline__ uint32_t sptr(const void* p) {
    return (uint32_t)__cvta_generic_to_shared(p);
}
__device__ __forceinline__ void ldsm4(uint32_t& r0, uint32_t& r1,
                                      uint32_t& r2, uint32_t& r3, uint32_t a) {
    asm volatile("ldmatrix.sync.aligned.m8n8.x4.shared.b16 {%0,%1,%2,%3}, [%4];"
                 : "=r"(r0), "=r"(r1), "=r"(r2), "=r"(r3) : "r"(a));
}
__device__ __forceinline__ void ldsm4t(uint32_t& r0, uint32_t& r1,
                                       uint32_t& r2, uint32_t& r3, uint32_t a) {
    asm volatile("ldmatrix.sync.aligned.m8n8.x4.trans.shared.b16 {%0,%1,%2,%3}, [%4];"
                 : "=r"(r0), "=r"(r1), "=r"(r2), "=r"(r3) : "r"(a));
}
__device__ __forceinline__ void ldsm2t(uint32_t& r0, uint32_t& r1, uint32_t a) {
    asm volatile("ldmatrix.sync.aligned.m8n8.x2.trans.shared.b16 {%0,%1}, [%2];"
                 : "=r"(r0), "=r"(r1) : "r"(a));
}
__device__ __forceinline__ void mma_f16(float* d, const uint32_t* a,
                                        const uint32_t* b) {
    asm volatile(
        "mma.sync.aligned.m16n8k16.row.col.f32.f16.f16.f32 "
        "{%0,%1,%2,%3}, {%4,%5,%6,%7}, {%8,%9}, {%0,%1,%2,%3};"
        : "+f"(d[0]), "+f"(d[1]), "+f"(d[2]), "+f"(d[3])
        : "r"(a[0]), "r"(a[1]), "r"(a[2]), "r"(a[3]), "r"(b[0]), "r"(b[1]));
}
__device__ __forceinline__ uint32_t ex2_h2(__half2 h) {
    uint32_t r;
    asm volatile("ex2.approx.f16x2 %0, %1;" : "=r"(r) : "r"(*(uint32_t*)&h));
    return r;
}
__device__ __forceinline__ void cpa16(uint32_t dst, const void* src) {
    asm volatile("cp.async.cg.shared.global [%0], [%1], 16;" :: "r"(dst), "l"(src));
}
__device__ __forceinline__ void cp_commit() {
    asm volatile("cp.async.commit_group;" ::: "memory");
}
template <int N>
__device__ __forceinline__ void cp_wait() {
    asm volatile("cp.async.wait_group %0;" :: "n"(N) : "memory");
}

// ---------------------------------------------------------------------------
// Kernel 0: fp32 -> fp16 convert (vectorized)
// ---------------------------------------------------------------------------
__global__ __launch_bounds__(256) void cvt_kernel(
    const float4* __restrict__ src, __half2* __restrict__ dst, int n4)
{
    int i = blockIdx.x * blockDim.x + threadIdx.x;
    if (i < n4) {
        float4 v = src[i];
        dst[2 * i + 0] = __floats2half2_rn(v.x, v.y);
        dst[2 * i + 1] = __floats2half2_rn(v.z, v.w);
    }
}

// ---------------------------------------------------------------------------
// Kernel 1: qkv = xh @ wh + b. 128x128 tile, BK=32, 3-stage cp.async pipeline.
// Epilogue: q scaled by 0.125*log2(e); masked V rows zeroed.
// ---------------------------------------------------------------------------
__global__ __launch_bounds__(256, 2) void qkv_gemm_kernel(
    const float* __restrict__ bias, const int* __restrict__ mask)
{
    extern __shared__ __align__(16) __half gsm[];
    __half* AsB = gsm;                    // 3 stages of [128][40]
    __half* BsB = gsm + 3 * 128 * 40;     // 3 stages of [32][136]

    const int bm = blockIdx.y, bn = blockIdx.x;
    const int tid = threadIdx.x;
    const int wid = tid >> 5, lane = tid & 31;
    const int wm = wid >> 2, wn = wid & 3;
    const int q = lane & 3, r = lane >> 2;

    auto stage = [&](int s, int k0) {
        __half* As = AsB + s * 128 * 40;
        __half* Bs = BsB + s * 32 * 136;
#pragma unroll
        for (int i = 0; i < 2; ++i) {
            int f = tid + i * 256;                 // 0..511
            int row = f >> 2, c8 = (f & 3) << 3;   // A: 128 x 32
            cpa16(sptr(&As[row * 40 + c8]),
                  g_xh + (size_t)(bm * 128 + row) * C_ + k0 + c8);
            int kr = f >> 4, n8 = (f & 15) << 3;   // B: 32 x 128
            cpa16(sptr(&Bs[kr * 136 + n8]),
                  g_wh + (size_t)(k0 + kr) * TC3 + bn * 128 + n8);
        }
    };

    float acc[4][4][4];
#pragma unroll
    for (int i = 0; i < 4; ++i)
#pragma unroll
        for (int j = 0; j < 4; ++j)
#pragma unroll
            for (int k = 0; k < 4; ++k) acc[i][j][k] = 0.f;

    stage(0, 0);  cp_commit();
    stage(1, 32); cp_commit();

    const int a_row = wm * 64 + (lane & 15);
    const int a_col = (lane >> 4) * 8;
    const int b_rowk = lane & 15;
    const int b_coln = (lane >> 4) * 8;

    for (int kt = 0; kt < 32; ++kt) {
        cp_wait<1>();
        __syncthreads();
        if (kt < 30) stage((kt + 2) % 3, (kt + 2) * 32);
        cp_commit();

        const __half* A  = AsB + (kt % 3) * 128 * 40;
        const __half* Bm = BsB + (kt % 3) * 32 * 136;
#pragma unroll
        for (int ks = 0; ks < 2; ++ks) {
            uint32_t af[4][4];
#pragma unroll
            for (int mt = 0; mt < 4; ++mt)
                ldsm4(af[mt][0], af[mt][1], af[mt][2], af[mt][3],
                      sptr(&A[(a_row + mt * 16) * 40 + ks * 16 + a_col]));
            uint32_t bf[4][2];
#pragma unroll
            for (int np = 0; np < 2; ++np) {
                uint32_t r0, r1, r2, r3;
                ldsm4t(r0, r1, r2, r3,
                       sptr(&Bm[(ks * 16 + b_rowk) * 136 + wn * 32 + np * 16 + b_coln]));
                bf[np * 2][0] = r0;     bf[np * 2][1] = r1;
                bf[np * 2 + 1][0] = r2; bf[np * 2 + 1][1] = r3;
            }
#pragma unroll
            for (int mt = 0; mt < 4; ++mt)
#pragma unroll
                for (int nt = 0; nt < 4; ++nt)
                    mma_f16(acc[mt][nt], af[mt], bf[nt]);
        }
    }

    // Epilogue: bias (+ q-scale / v-mask) + scatter fp16 into (B,H,T,D)
    const int which = bn >> 3;
    __half* dst = (which == 0) ? g_q : (which == 1) ? g_k : g_v;
    const float QSCALE = 0.18033688011112042f;   // 0.125 * log2(e)
#pragma unroll
    for (int mt = 0; mt < 4; ++mt) {
#pragma unroll
        for (int hf = 0; hf < 2; ++hf) {
            int m = bm * 128 + wm * 64 + mt * 16 + r + hf * 8;
            int bb = m >> 11, tt = m & 2047;
            float ms = 1.f;
            if (which == 0) ms = QSCALE;
            else if (which == 2) ms = mask[bb * T_ + tt] ? 1.f : 0.f;
#pragma unroll
            for (int nt = 0; nt < 4; ++nt) {
                int n = bn * 128 + wn * 32 + nt * 8 + 2 * q;
                int cc = n & 1023;
                int hh = cc >> 6, dd = cc & 63;
                float2 bv = *(const float2*)(bias + n);
                __half2 o = __floats2half2_rn((acc[mt][nt][hf * 2 + 0] + bv.x) * ms,
                                              (acc[mt][nt][hf * 2 + 1] + bv.y) * ms);
                *(__half2*)(dst + ((size_t)(bb * H_ + hh) * T_ + tt) * D_ + dd) = o;
            }
        }
    }
}

// ---------------------------------------------------------------------------
// Kernel 2: flash attention. 8 warps x 16 q-rows. P = 2^S via ex2.f16x2
// (scale folded into Q). Mask folded into V (rows zeroed) + 65th V column
// carries mask so l comes out of the PV mma. P stays in registers.
// ---------------------------------------------------------------------------
__global__ __launch_bounds__(256, 2) void attn_kernel(
    const int* __restrict__ mask, float* __restrict__ out)
{
    extern __shared__ __align__(16) __half asmem[];
    __half* Qs = asmem;                          // [128][72]
    __half* KsB = Qs + 128 * 72;                 // 2 x [64][72]
    __half* VsB = KsB + 2 * 64 * 72;             // 2 x [64][72]; col64=m, 65-71=0

    const int qb = blockIdx.x, h = blockIdx.y, b = blockIdx.z;
    const int tid = threadIdx.x;
    const int wid = tid >> 5, lane = tid & 31;
    const int q = lane & 3, r = lane >> 2;
    const int qr = wid * 16;

    const size_t bh = (size_t)(b * H_ + h);
    const __half* qptr  = g_q + (bh * T_ + (size_t)qb * 128) * D_;
    const __half* kbase = g_k + bh * T_ * D_;
    const __half* vbase = g_v + bh * T_ * D_;
    const int*    mbase = mask + (size_t)b * T_;

    auto stage = [&](int buf, int kb) {
        const __half* kp = kbase + (size_t)kb * 64 * D_;
        const __half* vp = vbase + (size_t)kb * 64 * D_;
        __half* Ks = KsB + buf * 64 * 72;
        __half* Vs = VsB + buf * 64 * 72;
#pragma unroll
        for (int i = 0; i < 2; ++i) {
            int f = tid + i * 256;                 // 0..511
            int row = f >> 3, c8 = (f & 7) << 3;
            cpa16(sptr(&Ks[row * 72 + c8]), kp + (size_t)row * D_ + c8);
            cpa16(sptr(&Vs[row * 72 + c8]), vp + (size_t)row * D_ + c8);
        }
        if (tid < 64) {
            __half2 m0 = __floats2half2_rn(mbase[kb * 64 + tid] ? 1.f : 0.f, 0.f);
            uint4 z;
            z.x = *(uint32_t*)&m0; z.y = 0; z.z = 0; z.w = 0;
            *(uint4*)&Vs[tid * 72 + 64] = z;
        }
    };

    stage(0, 0);
    cp_commit();

    // Stage Q, then load register-resident A fragments
#pragma unroll
    for (int i = 0; i < 4; ++i) {
        int f = tid + i * 256;
        int row = f >> 3, c8 = (f & 7) << 3;
        *(uint4*)&Qs[row * 72 + c8] = *(const uint4*)(qptr + (size_t)row * D_ + c8);
    }
    __syncthreads();

    uint32_t qf[4][4];
    const int a_row = qr + (lane & 15);
    const int a_col = (lane >> 4) * 8;
#pragma unroll
    for (int ks = 0; ks < 4; ++ks)
        ldsm4(qf[ks][0], qf[ks][1], qf[ks][2], qf[ks][3],
              sptr(&Qs[a_row * 72 + ks * 16 + a_col]));

    float oacc[9][4];
#pragma unroll
    for (int i = 0; i < 9; ++i)
#pragma unroll
        for (int j = 0; j < 4; ++j) oacc[i][j] = 0.f;

    const int b_row = (lane & 7) + ((lane & 16) ? 8 : 0);
    const int b_col = (lane & 8) ? 8 : 0;
    const int t_row = lane & 15;            // for ldsm.trans
    const int t_col = (lane >> 4) * 8;

    for (int kb = 0; kb < 32; ++kb) {
        const int buf = kb & 1;
        const __half* Ks = KsB + buf * 64 * 72;
        const __half* Vs = VsB + buf * 64 * 72;
        cp_wait<0>();
        __syncthreads();
        if (kb + 1 < 32) stage(buf ^ 1, kb + 1);
        cp_commit();

        // ---- S = Q.K^T (warp: 16 x 64); S already includes 0.125*log2e ----
        float sacc[8][4];
#pragma unroll
        for (int i = 0; i < 8; ++i)
#pragma unroll
            for (int j = 0; j < 4; ++j) sacc[i][j] = 0.f;
#pragma unroll
        for (int ks = 0; ks < 4; ++ks) {
            uint32_t kf[8][2];
#pragma unroll
            for (int np = 0; np < 4; ++np) {
                uint32_t r0, r1, r2, r3;
                ldsm4(r0, r1, r2, r3,
                      sptr(&Ks[(np * 16 + b_row) * 72 + ks * 16 + b_col]));
                kf[np * 2][0] = r0;     kf[np * 2][1] = r1;
                kf[np * 2 + 1][0] = r2; kf[np * 2 + 1][1] = r3;
            }
#pragma unroll
            for (int nt = 0; nt < 8; ++nt)
                mma_f16(sacc[nt], qf[ks], kf[nt]);
        }

        // ---- P = 2^S via f16x2 exp; pack straight into A-fragments ----
        uint32_t pf[4][4];
#pragma unroll
        for (int nt = 0; nt < 8; ++nt) {
            pf[nt >> 1][(nt & 1) * 2 + 0] =
                ex2_h2(__floats2half2_rn(sacc[nt][0], sacc[nt][1]));
            pf[nt >> 1][(nt & 1) * 2 + 1] =
                ex2_h2(__floats2half2_rn(sacc[nt][2], sacc[nt][3]));
        }

        // ---- O += P.V (9th n-tile carries l = P . mask-column) ----
#pragma unroll
        for (int ks2 = 0; ks2 < 4; ++ks2) {
            uint32_t vf[8][2];
#pragma unroll
            for (int np = 0; np < 4; ++np) {
                uint32_t r0, r1, r2, r3;
                ldsm4t(r0, r1, r2, r3,
                       sptr(&Vs[(ks2 * 16 + t_row) * 72 + np * 16 + t_col]));
                vf[np * 2][0] = r0;     vf[np * 2][1] = r1;
                vf[np * 2 + 1][0] = r2; vf[np * 2 + 1][1] = r3;
            }
            uint32_t v9[2];
            ldsm2t(v9[0], v9[1], sptr(&Vs[(ks2 * 16 + t_row) * 72 + 64]));
#pragma unroll
            for (int nt = 0; nt < 8; ++nt)
                mma_f16(oacc[nt], pf[ks2], vf[nt]);
            mma_f16(oacc[8], pf[ks2], v9);
        }
    }

    // l lives in col 64 -> n-tile 8, q==0 lanes: c0 (row r), c2 (row r+8)
    const int leader = lane & ~3;
    float l0 = __shfl_sync(0xffffffffu, oacc[8][0], leader);
    float l1 = __shfl_sync(0xffffffffu, oacc[8][2], leader);
    float inv0 = (l0 > 0.f) ? 1.f / l0 : 0.f;
    float inv1 = (l1 > 0.f) ? 1.f / l1 : 0.f;

    // Write out: index = b*T*C + h*T*D + t*D + d
    float* obase = out + (size_t)b * T_ * C_ + (size_t)h * T_ * D_;
    int row0 = qb * 128 + qr + r;
#pragma unroll
    for (int nt = 0; nt < 8; ++nt) {
        int dd = nt * 8 + 2 * q;
        float2 v0 = {oacc[nt][0] * inv0, oacc[nt][1] * inv0};
        float2 v1 = {oacc[nt][2] * inv1, oacc[nt][3] * inv1};
        *(float2*)(obase + (size_t)row0 * D_ + dd) = v0;
        *(float2*)(obase + (size_t)(row0 + 8) * D_ + dd) = v1;
    }
}

// ---------------------------------------------------------------------------
extern "C" void kernel_launch(void* const* d_in, const int* in_sizes, int n_in,
                              void* d_out, int out_size) {
    (void)in_sizes; (void)n_in; (void)out_size;
    const float* x    = (const float*)d_in[0];
    const int*   mask = (const int*)d_in[1];
    const float* W    = (const float*)d_in[2];
    const float* bias = (const float*)d_in[3];
    float*       out  = (float*)d_out;

    static __half2* xh_p = []() {
        void* p; cudaGetSymbolAddress(&p, g_xh); return (__half2*)p; }();
    static __half2* wh_p = []() {
        void* p; cudaGetSymbolAddress(&p, g_wh); return (__half2*)p; }();
    static int _once = []() {
        cudaFuncSetAttribute(qkv_gemm_kernel,
                             cudaFuncAttributeMaxDynamicSharedMemorySize, G_SMEM);
        cudaFuncSetAttribute(attn_kernel,
                             cudaFuncAttributeMaxDynamicSharedMemorySize, A_SMEM);
        return 0; }();
    (void)_once;

    int n4x = M_ * C_ / 4;
    int n4w = C_ * TC3 / 4;
    cvt_kernel<<<(n4x + 255) / 256, 256>>>((const float4*)x, xh_p, n4x);
    cvt_kernel<<<(n4w + 255) / 256, 256>>>((const float4*)W, wh_p, n4w);

    dim3 g1(TC3 / 128, M_ / 128);   // (24, 128)
    qkv_gemm_kernel<<<g1, 256, G_SMEM>>>(bias, mask);

    dim3 g2(T_ / 128, H_, B_);      // (16, 16, 8)
    attn_kernel<<<g2, 256, A_SMEM>>>(mask, out);
}

// round 9
// speedup vs baseline: 5.2582x; 1.0769x over previous
#include <cuda_runtime.h>
#include <cuda_fp16.h>
#include <cstdint>

static constexpr int B_  = 8;
static constexpr int T_  = 2048;
static constexpr int C_  = 1024;
static constexpr int H_  = 16;
static constexpr int D_  = 64;
static constexpr int TC3 = 3 * C_;
static constexpr int M_  = B_ * T_;

// Device scratch
__device__ __half g_xh[(size_t)M_ * C_];          // x in fp16
__device__ __half g_wh[(size_t)C_ * TC3];         // W in fp16
__device__ __half g_q[(size_t)B_ * H_ * T_ * D_]; // pre-scaled by 0.125*log2(e)
__device__ __half g_k[(size_t)B_ * H_ * T_ * D_];
__device__ __half g_v[(size_t)B_ * H_ * T_ * D_]; // masked rows zeroed

// Dynamic smem sizes
static constexpr int G_SMEM = (3 * 128 * 40 + 3 * 32 * 136) * 2;            // 56832 B
static constexpr int A_SMEM = (128 * 72 + 2 * 64 * 72 + 2 * 64 * 72) * 2;   // 55296 B

// ---------------------------------------------------------------------------
__device__ __forceinline__ uint32_t sptr(const void* p) {
    return (uint32_t)__cvta_generic_to_shared(p);
}
__device__ __forceinline__ void ldsm4(uint32_t& r0, uint32_t& r1,
                                      uint32_t& r2, uint32_t& r3, uint32_t a) {
    asm volatile("ldmatrix.sync.aligned.m8n8.x4.shared.b16 {%0,%1,%2,%3}, [%4];"
                 : "=r"(r0), "=r"(r1), "=r"(r2), "=r"(r3) : "r"(a));
}
__device__ __forceinline__ void ldsm4t(uint32_t& r0, uint32_t& r1,
                                       uint32_t& r2, uint32_t& r3, uint32_t a) {
    asm volatile("ldmatrix.sync.aligned.m8n8.x4.trans.shared.b16 {%0,%1,%2,%3}, [%4];"
                 : "=r"(r0), "=r"(r1), "=r"(r2), "=r"(r3) : "r"(a));
}
__device__ __forceinline__ void ldsm2t(uint32_t& r0, uint32_t& r1, uint32_t a) {
    asm volatile("ldmatrix.sync.aligned.m8n8.x2.trans.shared.b16 {%0,%1}, [%2];"
                 : "=r"(r0), "=r"(r1) : "r"(a));
}
__device__ __forceinline__ void mma_f16(float* d, const uint32_t* a,
                                        const uint32_t* b) {
    asm volatile(
        "mma.sync.aligned.m16n8k16.row.col.f32.f16.f16.f32 "
        "{%0,%1,%2,%3}, {%4,%5,%6,%7}, {%8,%9}, {%0,%1,%2,%3};"
        : "+f"(d[0]), "+f"(d[1]), "+f"(d[2]), "+f"(d[3])
        : "r"(a[0]), "r"(a[1]), "r"(a[2]), "r"(a[3]), "r"(b[0]), "r"(b[1]));
}
__device__ __forceinline__ uint32_t ex2_h2(__half2 h) {
    uint32_t r;
    asm volatile("ex2.approx.f16x2 %0, %1;" : "=r"(r) : "r"(*(uint32_t*)&h));
    return r;
}
__device__ __forceinline__ void cpa16(uint32_t dst, const void* src) {
    asm volatile("cp.async.cg.shared.global [%0], [%1], 16;" :: "r"(dst), "l"(src));
}
__device__ __forceinline__ void cp_commit() {
    asm volatile("cp.async.commit_group;" ::: "memory");
}
template <int N>
__device__ __forceinline__ void cp_wait() {
    asm volatile("cp.async.wait_group %0;" :: "n"(N) : "memory");
}

// ---------------------------------------------------------------------------
// Kernel 0: fp32 -> fp16 convert (vectorized)
// ---------------------------------------------------------------------------
__global__ __launch_bounds__(256) void cvt_kernel(
    const float4* __restrict__ src, __half2* __restrict__ dst, int n4)
{
    int i = blockIdx.x * blockDim.x + threadIdx.x;
    if (i < n4) {
        float4 v = src[i];
        dst[2 * i + 0] = __floats2half2_rn(v.x, v.y);
        dst[2 * i + 1] = __floats2half2_rn(v.z, v.w);
    }
}

// ---------------------------------------------------------------------------
// Kernel 1: qkv = xh @ wh + b. 128x128 tile, BK=32, 3-stage cp.async pipeline.
// 4 warps (2x2), warp tile 64x64 — 2x fragment amortization.
// Epilogue: q scaled by 0.125*log2(e); masked V rows zeroed.
// ---------------------------------------------------------------------------
__global__ __launch_bounds__(128, 2) void qkv_gemm_kernel(
    const float* __restrict__ bias, const int* __restrict__ mask)
{
    extern __shared__ __align__(16) __half gsm[];
    __half* AsB = gsm;                    // 3 stages of [128][40]
    __half* BsB = gsm + 3 * 128 * 40;     // 3 stages of [32][136]

    const int bm = blockIdx.y, bn = blockIdx.x;
    const int tid = threadIdx.x;
    const int wid = tid >> 5, lane = tid & 31;
    const int wm = wid >> 1, wn = wid & 1;          // 2x2 warp grid, 64x64 tiles
    const int q = lane & 3, r = lane >> 2;

    auto stage = [&](int s, int k0) {
        __half* As = AsB + s * 128 * 40;
        __half* Bs = BsB + s * 32 * 136;
#pragma unroll
        for (int i = 0; i < 4; ++i) {
            int f = tid + i * 128;                 // 0..511
            int row = f >> 2, c8 = (f & 3) << 3;   // A: 128 x 32
            cpa16(sptr(&As[row * 40 + c8]),
                  g_xh + (size_t)(bm * 128 + row) * C_ + k0 + c8);
            int kr = f >> 4, n8 = (f & 15) << 3;   // B: 32 x 128
            cpa16(sptr(&Bs[kr * 136 + n8]),
                  g_wh + (size_t)(k0 + kr) * TC3 + bn * 128 + n8);
        }
    };

    float acc[4][8][4];
#pragma unroll
    for (int i = 0; i < 4; ++i)
#pragma unroll
        for (int j = 0; j < 8; ++j)
#pragma unroll
            for (int k = 0; k < 4; ++k) acc[i][j][k] = 0.f;

    stage(0, 0);  cp_commit();
    stage(1, 32); cp_commit();

    const int a_row = wm * 64 + (lane & 15);
    const int a_col = (lane >> 4) * 8;
    const int b_rowk = lane & 15;
    const int b_coln = (lane >> 4) * 8;

    for (int kt = 0; kt < 32; ++kt) {
        cp_wait<1>();
        __syncthreads();
        if (kt < 30) stage((kt + 2) % 3, (kt + 2) * 32);
        cp_commit();

        const __half* A  = AsB + (kt % 3) * 128 * 40;
        const __half* Bm = BsB + (kt % 3) * 32 * 136;
#pragma unroll
        for (int ks = 0; ks < 2; ++ks) {
            uint32_t af[4][4];
#pragma unroll
            for (int mt = 0; mt < 4; ++mt)
                ldsm4(af[mt][0], af[mt][1], af[mt][2], af[mt][3],
                      sptr(&A[(a_row + mt * 16) * 40 + ks * 16 + a_col]));
            uint32_t bf[8][2];
#pragma unroll
            for (int np = 0; np < 4; ++np) {
                uint32_t r0, r1, r2, r3;
                ldsm4t(r0, r1, r2, r3,
                       sptr(&Bm[(ks * 16 + b_rowk) * 136 + wn * 64 + np * 16 + b_coln]));
                bf[np * 2][0] = r0;     bf[np * 2][1] = r1;
                bf[np * 2 + 1][0] = r2; bf[np * 2 + 1][1] = r3;
            }
#pragma unroll
            for (int mt = 0; mt < 4; ++mt)
#pragma unroll
                for (int nt = 0; nt < 8; ++nt)
                    mma_f16(acc[mt][nt], af[mt], bf[nt]);
        }
    }

    // Epilogue: bias (+ q-scale / v-mask) + scatter fp16 into (B,H,T,D)
    const int which = bn >> 3;
    __half* dst = (which == 0) ? g_q : (which == 1) ? g_k : g_v;
    const float QSCALE = 0.18033688011112042f;   // 0.125 * log2(e)
#pragma unroll
    for (int mt = 0; mt < 4; ++mt) {
#pragma unroll
        for (int hf = 0; hf < 2; ++hf) {
            int m = bm * 128 + wm * 64 + mt * 16 + r + hf * 8;
            int bb = m >> 11, tt = m & 2047;
            float ms = 1.f;
            if (which == 0) ms = QSCALE;
            else if (which == 2) ms = mask[bb * T_ + tt] ? 1.f : 0.f;
#pragma unroll
            for (int nt = 0; nt < 8; ++nt) {
                int n = bn * 128 + wn * 64 + nt * 8 + 2 * q;
                int cc = n & 1023;
                int hh = cc >> 6, dd = cc & 63;
                float2 bv = *(const float2*)(bias + n);
                __half2 o = __floats2half2_rn((acc[mt][nt][hf * 2 + 0] + bv.x) * ms,
                                              (acc[mt][nt][hf * 2 + 1] + bv.y) * ms);
                *(__half2*)(dst + ((size_t)(bb * H_ + hh) * T_ + tt) * D_ + dd) = o;
            }
        }
    }
}

// ---------------------------------------------------------------------------
// Kernel 2: flash attention. 4 warps x 32 q-rows (2x fragment amortization).
// P = 2^S via ex2.f16x2 (scale folded into Q). Mask folded into V + 65th V
// column carries l via the PV mma. P stays in registers.
// ---------------------------------------------------------------------------
__global__ __launch_bounds__(128, 2) void attn_kernel(
    const int* __restrict__ mask, float* __restrict__ out)
{
    extern __shared__ __align__(16) __half asmem[];
    __half* Qs = asmem;                          // [128][72]
    __half* KsB = Qs + 128 * 72;                 // 2 x [64][72]
    __half* VsB = KsB + 2 * 64 * 72;             // 2 x [64][72]; col64=m, 65-71=0

    const int qb = blockIdx.x, h = blockIdx.y, b = blockIdx.z;
    const int tid = threadIdx.x;
    const int wid = tid >> 5, lane = tid & 31;
    const int q = lane & 3, r = lane >> 2;
    const int qr = wid * 32;                      // warp's 32 q-rows

    const size_t bh = (size_t)(b * H_ + h);
    const __half* qptr  = g_q + (bh * T_ + (size_t)qb * 128) * D_;
    const __half* kbase = g_k + bh * T_ * D_;
    const __half* vbase = g_v + bh * T_ * D_;
    const int*    mbase = mask + (size_t)b * T_;

    auto stage = [&](int buf, int kb) {
        const __half* kp = kbase + (size_t)kb * 64 * D_;
        const __half* vp = vbase + (size_t)kb * 64 * D_;
        __half* Ks = KsB + buf * 64 * 72;
        __half* Vs = VsB + buf * 64 * 72;
#pragma unroll
        for (int i = 0; i < 4; ++i) {
            int f = tid + i * 128;                 // 0..511
            int row = f >> 3, c8 = (f & 7) << 3;
            cpa16(sptr(&Ks[row * 72 + c8]), kp + (size_t)row * D_ + c8);
            cpa16(sptr(&Vs[row * 72 + c8]), vp + (size_t)row * D_ + c8);
        }
        if (tid < 64) {
            __half2 m0 = __floats2half2_rn(mbase[kb * 64 + tid] ? 1.f : 0.f, 0.f);
            uint4 z;
            z.x = *(uint32_t*)&m0; z.y = 0; z.z = 0; z.w = 0;
            *(uint4*)&Vs[tid * 72 + 64] = z;
        }
    };

    stage(0, 0);
    cp_commit();

    // Stage Q, then load register-resident A fragments (2 half-tiles x 4 ks)
#pragma unroll
    for (int i = 0; i < 8; ++i) {
        int f = tid + i * 128;
        int row = f >> 3, c8 = (f & 7) << 3;
        *(uint4*)&Qs[row * 72 + c8] = *(const uint4*)(qptr + (size_t)row * D_ + c8);
    }
    __syncthreads();

    uint32_t qf[2][4][4];
    const int a_col = (lane >> 4) * 8;
#pragma unroll
    for (int hh = 0; hh < 2; ++hh) {
        const int a_row = qr + hh * 16 + (lane & 15);
#pragma unroll
        for (int ks = 0; ks < 4; ++ks)
            ldsm4(qf[hh][ks][0], qf[hh][ks][1], qf[hh][ks][2], qf[hh][ks][3],
                  sptr(&Qs[a_row * 72 + ks * 16 + a_col]));
    }

    float oacc[2][9][4];
#pragma unroll
    for (int hh = 0; hh < 2; ++hh)
#pragma unroll
        for (int i = 0; i < 9; ++i)
#pragma unroll
            for (int j = 0; j < 4; ++j) oacc[hh][i][j] = 0.f;

    const int b_row = (lane & 7) + ((lane & 16) ? 8 : 0);
    const int b_col = (lane & 8) ? 8 : 0;
    const int t_row = lane & 15;            // for ldsm.trans
    const int t_col = (lane >> 4) * 8;

    for (int kb = 0; kb < 32; ++kb) {
        const int buf = kb & 1;
        const __half* Ks = KsB + buf * 64 * 72;
        const __half* Vs = VsB + buf * 64 * 72;
        cp_wait<0>();
        __syncthreads();
        if (kb + 1 < 32) stage(buf ^ 1, kb + 1);
        cp_commit();

        // ---- S = Q.K^T (warp: 32 x 64); kf shared by both half-tiles ----
        float sacc[2][8][4];
#pragma unroll
        for (int hh = 0; hh < 2; ++hh)
#pragma unroll
            for (int i = 0; i < 8; ++i)
#pragma unroll
                for (int j = 0; j < 4; ++j) sacc[hh][i][j] = 0.f;
#pragma unroll
        for (int ks = 0; ks < 4; ++ks) {
            uint32_t kf[8][2];
#pragma unroll
            for (int np = 0; np < 4; ++np) {
                uint32_t r0, r1, r2, r3;
                ldsm4(r0, r1, r2, r3,
                      sptr(&Ks[(np * 16 + b_row) * 72 + ks * 16 + b_col]));
                kf[np * 2][0] = r0;     kf[np * 2][1] = r1;
                kf[np * 2 + 1][0] = r2; kf[np * 2 + 1][1] = r3;
            }
#pragma unroll
            for (int hh = 0; hh < 2; ++hh)
#pragma unroll
                for (int nt = 0; nt < 8; ++nt)
                    mma_f16(sacc[hh][nt], qf[hh][ks], kf[nt]);
        }

        // ---- P = 2^S via f16x2 exp; pack straight into A-fragments ----
        uint32_t pf[2][4][4];
#pragma unroll
        for (int hh = 0; hh < 2; ++hh)
#pragma unroll
            for (int nt = 0; nt < 8; ++nt) {
                pf[hh][nt >> 1][(nt & 1) * 2 + 0] =
                    ex2_h2(__floats2half2_rn(sacc[hh][nt][0], sacc[hh][nt][1]));
                pf[hh][nt >> 1][(nt & 1) * 2 + 1] =
                    ex2_h2(__floats2half2_rn(sacc[hh][nt][2], sacc[hh][nt][3]));
            }

        // ---- O += P.V (9th n-tile carries l); vf shared by both halves ----
#pragma unroll
        for (int ks2 = 0; ks2 < 4; ++ks2) {
            uint32_t vf[8][2];
#pragma unroll
            for (int np = 0; np < 4; ++np) {
                uint32_t r0, r1, r2, r3;
                ldsm4t(r0, r1, r2, r3,
                       sptr(&Vs[(ks2 * 16 + t_row) * 72 + np * 16 + t_col]));
                vf[np * 2][0] = r0;     vf[np * 2][1] = r1;
                vf[np * 2 + 1][0] = r2; vf[np * 2 + 1][1] = r3;
            }
            uint32_t v9[2];
            ldsm2t(v9[0], v9[1], sptr(&Vs[(ks2 * 16 + t_row) * 72 + 64]));
#pragma unroll
            for (int hh = 0; hh < 2; ++hh) {
#pragma unroll
                for (int nt = 0; nt < 8; ++nt)
                    mma_f16(oacc[hh][nt], pf[hh][ks2], vf[nt]);
                mma_f16(oacc[hh][8], pf[hh][ks2], v9);
            }
        }
    }

    // l lives in col 64 (n-tile 8): c0 -> row r, c2 -> row r+8, from q==0 lane
    const int leader = lane & ~3;
    float* obase = out + (size_t)b * T_ * C_ + (size_t)h * T_ * D_;
#pragma unroll
    for (int hh = 0; hh < 2; ++hh) {
        float l0 = __shfl_sync(0xffffffffu, oacc[hh][8][0], leader);
        float l1 = __shfl_sync(0xffffffffu, oacc[hh][8][2], leader);
        float inv0 = (l0 > 0.f) ? 1.f / l0 : 0.f;
        float inv1 = (l1 > 0.f) ? 1.f / l1 : 0.f;
        int row0 = qb * 128 + qr + hh * 16 + r;
#pragma unroll
        for (int nt = 0; nt < 8; ++nt) {
            int dd = nt * 8 + 2 * q;
            float2 v0 = {oacc[hh][nt][0] * inv0, oacc[hh][nt][1] * inv0};
            float2 v1 = {oacc[hh][nt][2] * inv1, oacc[hh][nt][3] * inv1};
            *(float2*)(obase + (size_t)row0 * D_ + dd) = v0;
            *(float2*)(obase + (size_t)(row0 + 8) * D_ + dd) = v1;
        }
    }
}

// ---------------------------------------------------------------------------
extern "C" void kernel_launch(void* const* d_in, const int* in_sizes, int n_in,
                              void* d_out, int out_size) {
    (void)in_sizes; (void)n_in; (void)out_size;
    const float* x    = (const float*)d_in[0];
    const int*   mask = (const int*)d_in[1];
    const float* W    = (const float*)d_in[2];
    const float* bias = (const float*)d_in[3];
    float*       out  = (float*)d_out;

    static __half2* xh_p = []() {
        void* p; cudaGetSymbolAddress(&p, g_xh); return (__half2*)p; }();
    static __half2* wh_p = []() {
        void* p; cudaGetSymbolAddress(&p, g_wh); return (__half2*)p; }();
    static int _once = []() {
        cudaFuncSetAttribute(qkv_gemm_kernel,
                             cudaFuncAttributeMaxDynamicSharedMemorySize, G_SMEM);
        cudaFuncSetAttribute(attn_kernel,
                             cudaFuncAttributeMaxDynamicSharedMemorySize, A_SMEM);
        return 0; }();
    (void)_once;

    int n4x = M_ * C_ / 4;
    int n4w = C_ * TC3 / 4;
    cvt_kernel<<<(n4x + 255) / 256, 256>>>((const float4*)x, xh_p, n4x);
    cvt_kernel<<<(n4w + 255) / 256, 256>>>((const float4*)W, wh_p, n4w);

    dim3 g1(TC3 / 128, M_ / 128);   // (24, 128)
    qkv_gemm_kernel<<<g1, 128, G_SMEM>>>(bias, mask);

    dim3 g2(T_ / 128, H_, B_);      // (16, 16, 8)
    attn_kernel<<<g2, 128, A_SMEM>>>(mask, out);
}